// round 1
// baseline (speedup 1.0000x reference)
#include <cuda_runtime.h>
#include <cuda_fp16.h>
#include <cstdint>
#include <cstddef>

// ---------------------------------------------------------------------------
// GPT-2 transformer block, fp16 tensor-core (mma.sync) implementation.
// B=4, S=2048, D=1024, H=16, hd=64, DFF=4096. fp32 in/out, fp16 compute,
// fp32 accumulation everywhere.
// ---------------------------------------------------------------------------

#define BATCH  4
#define SEQ    2048
#define DMODEL 1024
#define NHEAD  16
#define HDIM   64
#define DFF    4096
#define ROWS   (BATCH * SEQ)   // 8192

// -------------------------- scratch (device globals) ----------------------
__device__ __half g_x16    [(size_t)ROWS * DMODEL];
__device__ __half g_wattnT [(size_t)3 * DMODEL * DMODEL];   // [3D][D]
__device__ __half g_waprojT[(size_t)DMODEL * DMODEL];       // [D][D]
__device__ __half g_wfcT   [(size_t)DFF * DMODEL];          // [DFF][D]
__device__ __half g_wmprojT[(size_t)DMODEL * DFF];          // [D][DFF]
__device__ __half g_q16    [(size_t)ROWS * DMODEL];         // [B*H][S][hd]
__device__ __half g_k16    [(size_t)ROWS * DMODEL];
__device__ __half g_v16    [(size_t)ROWS * DMODEL];
__device__ __half g_a16    [(size_t)ROWS * DMODEL];         // attn out, [r][D]
__device__ float  g_ap32   [(size_t)ROWS * DMODEL];
__device__ float  g_n32    [(size_t)ROWS * DMODEL];
__device__ __half g_n16    [(size_t)ROWS * DMODEL];
__device__ __half g_h16    [(size_t)ROWS * DFF];
__device__ float  g_m32    [(size_t)ROWS * DMODEL];

// ------------------------------ helpers -----------------------------------
__device__ __forceinline__ void mma16816(float c[4], const uint32_t a[4],
                                         const uint32_t b[2]) {
    asm volatile(
        "mma.sync.aligned.m16n8k16.row.col.f32.f16.f16.f32 "
        "{%0,%1,%2,%3}, {%4,%5,%6,%7}, {%8,%9}, {%0,%1,%2,%3};\n"
        : "+f"(c[0]), "+f"(c[1]), "+f"(c[2]), "+f"(c[3])
        : "r"(a[0]), "r"(a[1]), "r"(a[2]), "r"(a[3]), "r"(b[0]), "r"(b[1]));
}

__device__ __forceinline__ void cp_async16(void* smem, const void* gptr) {
    uint32_t s = (uint32_t)__cvta_generic_to_shared(smem);
    asm volatile("cp.async.cg.shared.global [%0], [%1], 16;\n" ::"r"(s), "l"(gptr));
}
#define CP_COMMIT() asm volatile("cp.async.commit_group;\n" ::)
#define CP_WAIT1()  asm volatile("cp.async.wait_group 1;\n" ::)

__device__ __forceinline__ uint32_t pack_half2f(float a, float b) {
    __half2 h = __floats2half2_rn(a, b);
    return *reinterpret_cast<uint32_t*>(&h);
}

__device__ __forceinline__ float gelu_f(float x) {
    const float k0 = 0.7978845608028654f;  // sqrt(2/pi)
    float t = tanhf(k0 * (x + 0.044715f * x * x * x));
    return 0.5f * x * (1.0f + t);
}

// ------------------------- conversion kernels -----------------------------
__global__ void cvt_f32_to_f16(const float* __restrict__ in,
                               __half* __restrict__ out, int n) {
    int i = blockIdx.x * blockDim.x + threadIdx.x;
    if (i < n) out[i] = __float2half(in[i]);
}

// in: [R][C] fp32 row-major  ->  out: [C][R] fp16
__global__ void transpose_cvt(const float* __restrict__ in,
                              __half* __restrict__ out, int R, int C) {
    __shared__ float t[32][33];
    int c = blockIdx.x * 32 + threadIdx.x;
    int r = blockIdx.y * 32 + threadIdx.y;
#pragma unroll
    for (int i = 0; i < 32; i += 8)
        t[threadIdx.y + i][threadIdx.x] = in[(size_t)(r + i) * C + c];
    __syncthreads();
    int oc   = blockIdx.y * 32 + threadIdx.x;   // output col = original row
    int orow = blockIdx.x * 32 + threadIdx.y;   // output row = original col
#pragma unroll
    for (int i = 0; i < 32; i += 8)
        out[(size_t)(orow + i) * R + oc] = __float2half(t[threadIdx.x][threadIdx.y + i]);
}

// ------------------------------- GEMM -------------------------------------
// C[M,N] = A[M,K] (fp16 row-major) * Bt[N,K] (fp16, i.e. B col-major) + bias
// BM=BN=128, BK=32, 256 threads, warp grid 2x4, warp tile 64x32.
#define GB_BM 128
#define GB_BN 128
#define GB_BK 32
#define GB_LK 40   // padded shared K stride (halves)

enum { EPI_QKV = 0, EPI_F32 = 1, EPI_GELU = 2 };

template <int EPI>
__global__ __launch_bounds__(256, 2) void gemm_kernel(
    const __half* __restrict__ A, const __half* __restrict__ Bt,
    const float* __restrict__ bias,
    float* __restrict__ outF, __half* __restrict__ outH,
    __half* __restrict__ oq, __half* __restrict__ ok, __half* __restrict__ ov,
    int M, int N, int K) {
    __shared__ __half As[2][GB_BM][GB_LK];
    __shared__ __half Bs[2][GB_BN][GB_LK];

    const int tid  = threadIdx.x;
    const int warp = tid >> 5, lane = tid & 31;
    const int g = lane >> 2, tg = lane & 3;
    const int wm = warp >> 2, wn = warp & 3;
    const int bm = blockIdx.y * GB_BM, bn = blockIdx.x * GB_BN;

    float acc[4][4][4];
#pragma unroll
    for (int i = 0; i < 4; i++)
#pragma unroll
        for (int j = 0; j < 4; j++)
#pragma unroll
            for (int q = 0; q < 4; q++) acc[i][j][q] = 0.f;

    const int KT = K / GB_BK;

    auto load_tile = [&](int kt, int buf) {
        int k0 = kt * GB_BK;
#pragma unroll
        for (int i = 0; i < 2; i++) {
            int c   = tid + i * 256;
            int row = c >> 2;
            int kc  = (c & 3) * 8;
            cp_async16(&As[buf][row][kc], &A[(size_t)(bm + row) * K + k0 + kc]);
            cp_async16(&Bs[buf][row][kc], &Bt[(size_t)(bn + row) * K + k0 + kc]);
        }
    };

    load_tile(0, 0); CP_COMMIT();
    load_tile(1, 1); CP_COMMIT();

    for (int t = 0; t < KT; t++) {
        CP_WAIT1();
        __syncthreads();
        int buf = t & 1;
#pragma unroll
        for (int kk = 0; kk < 2; kk++) {
            int kb = kk * 16 + tg * 2;
            uint32_t a[4][4], b[4][2];
#pragma unroll
            for (int mi = 0; mi < 4; mi++) {
                int r = wm * 64 + mi * 16 + g;
                a[mi][0] = *reinterpret_cast<const uint32_t*>(&As[buf][r][kb]);
                a[mi][1] = *reinterpret_cast<const uint32_t*>(&As[buf][r + 8][kb]);
                a[mi][2] = *reinterpret_cast<const uint32_t*>(&As[buf][r][kb + 8]);
                a[mi][3] = *reinterpret_cast<const uint32_t*>(&As[buf][r + 8][kb + 8]);
            }
#pragma unroll
            for (int ni = 0; ni < 4; ni++) {
                int c = wn * 32 + ni * 8 + g;
                b[ni][0] = *reinterpret_cast<const uint32_t*>(&Bs[buf][c][kb]);
                b[ni][1] = *reinterpret_cast<const uint32_t*>(&Bs[buf][c][kb + 8]);
            }
#pragma unroll
            for (int mi = 0; mi < 4; mi++)
#pragma unroll
                for (int ni = 0; ni < 4; ni++) mma16816(acc[mi][ni], a[mi], b[ni]);
        }
        __syncthreads();
        if (t + 2 < KT) load_tile(t + 2, buf);
        CP_COMMIT();
    }

    // ------------------------------ epilogue -------------------------------
#pragma unroll
    for (int mi = 0; mi < 4; mi++) {
        int r0 = bm + wm * 64 + mi * 16 + g;
        int r1 = r0 + 8;
#pragma unroll
        for (int ni = 0; ni < 4; ni++) {
            int c0 = bn + wn * 32 + ni * 8 + tg * 2;
            float bv0 = bias[c0], bv1 = bias[c0 + 1];
            float v00 = acc[mi][ni][0] + bv0, v01 = acc[mi][ni][1] + bv1;
            float v10 = acc[mi][ni][2] + bv0, v11 = acc[mi][ni][3] + bv1;
            if (EPI == EPI_F32) {
                outF[(size_t)r0 * N + c0]     = v00;
                outF[(size_t)r0 * N + c0 + 1] = v01;
                outF[(size_t)r1 * N + c0]     = v10;
                outF[(size_t)r1 * N + c0 + 1] = v11;
            } else if (EPI == EPI_GELU) {
                outH[(size_t)r0 * N + c0]     = __float2half(gelu_f(v00));
                outH[(size_t)r0 * N + c0 + 1] = __float2half(gelu_f(v01));
                outH[(size_t)r1 * N + c0]     = __float2half(gelu_f(v10));
                outH[(size_t)r1 * N + c0 + 1] = __float2half(gelu_f(v11));
            } else {  // EPI_QKV: scatter into per-head [B*H][S][hd] layout
#pragma unroll
                for (int e = 0; e < 4; e++) {
                    int r = (e < 2) ? r0 : r1;
                    int c = c0 + (e & 1);
                    float val = (e == 0) ? v00 : (e == 1) ? v01 : (e == 2) ? v10 : v11;
                    int which = c >> 10;
                    int cc = c & 1023;
                    int h = cc >> 6, d = cc & 63;
                    int b = r >> 11, s = r & 2047;
                    size_t idx = ((size_t)(b * NHEAD + h) * SEQ + s) * HDIM + d;
                    __half* dst = which == 0 ? oq : which == 1 ? ok : ov;
                    dst[idx] = __float2half(val);
                }
            }
        }
    }
}

// --------------------------- flash attention -------------------------------
// grid (S/128, B*H), 256 threads (8 warps x 16 query rows). Causal.
#define AT_BQ 128
#define AT_BK 128
#define AT_LK 72    // Ks row stride (halves)
#define AT_LV 138   // Vt row stride (halves)

__global__ __launch_bounds__(256, 1) void attn_kernel(
    const __half* __restrict__ Q, const __half* __restrict__ K,
    const __half* __restrict__ V, __half* __restrict__ Aout) {
    __shared__ __half Ks[AT_BK][AT_LK];
    __shared__ __half Vt[HDIM][AT_LV];

    const int tid  = threadIdx.x;
    const int warp = tid >> 5, lane = tid & 31;
    const int g = lane >> 2, tg = lane & 3;
    const int bh = blockIdx.y;
    const int qb = blockIdx.x;
    const size_t base = (size_t)bh * SEQ * HDIM;

    // stage Q tile through Ks, then lift fragments into registers
    for (int i = tid; i < AT_BQ * 8; i += 256) {
        int row = i >> 3, ch = (i & 7) * 8;
        *reinterpret_cast<uint4*>(&Ks[row][ch]) =
            *reinterpret_cast<const uint4*>(&Q[base + (size_t)(qb * AT_BQ + row) * HDIM + ch]);
    }
    __syncthreads();
    uint32_t qa[4][4];
    {
        int r = warp * 16 + g;
#pragma unroll
        for (int kt = 0; kt < 4; kt++) {
            int kb = kt * 16 + tg * 2;
            qa[kt][0] = *reinterpret_cast<const uint32_t*>(&Ks[r][kb]);
            qa[kt][1] = *reinterpret_cast<const uint32_t*>(&Ks[r + 8][kb]);
            qa[kt][2] = *reinterpret_cast<const uint32_t*>(&Ks[r][kb + 8]);
            qa[kt][3] = *reinterpret_cast<const uint32_t*>(&Ks[r + 8][kb + 8]);
        }
    }
    __syncthreads();

    float o[8][4];
#pragma unroll
    for (int i = 0; i < 8; i++)
#pragma unroll
        for (int j = 0; j < 4; j++) o[i][j] = 0.f;
    float m0 = -1e30f, m1 = -1e30f, l0 = 0.f, l1 = 0.f;
    const int q0 = qb * AT_BQ + warp * 16 + g;
    const int q1 = q0 + 8;

    for (int kblk = 0; kblk <= qb; kblk++) {
        // load K tile (k-major) and V tile transposed
        for (int i = tid; i < AT_BK * 8; i += 256) {
            int row = i >> 3, ch = (i & 7) * 8;
            *reinterpret_cast<uint4*>(&Ks[row][ch]) =
                *reinterpret_cast<const uint4*>(&K[base + (size_t)(kblk * AT_BK + row) * HDIM + ch]);
        }
        for (int i = tid; i < AT_BK * HDIM; i += 256) {
            int s = i >> 6, d = i & 63;
            Vt[d][s] = V[base + (size_t)(kblk * AT_BK + s) * HDIM + d];
        }
        __syncthreads();

        // S = Q K^T
        float sacc[16][4];
#pragma unroll
        for (int nt = 0; nt < 16; nt++)
#pragma unroll
            for (int j = 0; j < 4; j++) sacc[nt][j] = 0.f;
#pragma unroll
        for (int kt = 0; kt < 4; kt++) {
#pragma unroll
            for (int nt = 0; nt < 16; nt++) {
                uint32_t b[2];
                int col = nt * 8 + g;
                int kb = kt * 16 + tg * 2;
                b[0] = *reinterpret_cast<const uint32_t*>(&Ks[col][kb]);
                b[1] = *reinterpret_cast<const uint32_t*>(&Ks[col][kb + 8]);
                mma16816(sacc[nt], qa[kt], b);
            }
        }

        // scale + causal mask
        const float scale = 0.125f;  // 1/sqrt(64)
        const int kbase = kblk * AT_BK;
#pragma unroll
        for (int nt = 0; nt < 16; nt++) {
            int c0 = kbase + nt * 8 + tg * 2;
            sacc[nt][0] *= scale; sacc[nt][1] *= scale;
            sacc[nt][2] *= scale; sacc[nt][3] *= scale;
            if (kblk == qb) {
                if (c0 > q0)     sacc[nt][0] = -1e30f;
                if (c0 + 1 > q0) sacc[nt][1] = -1e30f;
                if (c0 > q1)     sacc[nt][2] = -1e30f;
                if (c0 + 1 > q1) sacc[nt][3] = -1e30f;
            }
        }

        // online softmax
        float nm0 = m0, nm1 = m1;
#pragma unroll
        for (int nt = 0; nt < 16; nt++) {
            nm0 = fmaxf(nm0, fmaxf(sacc[nt][0], sacc[nt][1]));
            nm1 = fmaxf(nm1, fmaxf(sacc[nt][2], sacc[nt][3]));
        }
        nm0 = fmaxf(nm0, __shfl_xor_sync(0xffffffffu, nm0, 1));
        nm0 = fmaxf(nm0, __shfl_xor_sync(0xffffffffu, nm0, 2));
        nm1 = fmaxf(nm1, __shfl_xor_sync(0xffffffffu, nm1, 1));
        nm1 = fmaxf(nm1, __shfl_xor_sync(0xffffffffu, nm1, 2));
        float alpha0 = __expf(m0 - nm0), alpha1 = __expf(m1 - nm1);

        float ls0 = 0.f, ls1 = 0.f;
        uint32_t pa[8][4];
#pragma unroll
        for (int nt = 0; nt < 16; nt++) {
            float p00 = __expf(sacc[nt][0] - nm0);
            float p01 = __expf(sacc[nt][1] - nm0);
            float p10 = __expf(sacc[nt][2] - nm1);
            float p11 = __expf(sacc[nt][3] - nm1);
            ls0 += p00 + p01;
            ls1 += p10 + p11;
            int kt = nt >> 1, hi = nt & 1;
            pa[kt][hi * 2 + 0] = pack_half2f(p00, p01);
            pa[kt][hi * 2 + 1] = pack_half2f(p10, p11);
        }
        ls0 += __shfl_xor_sync(0xffffffffu, ls0, 1);
        ls0 += __shfl_xor_sync(0xffffffffu, ls0, 2);
        ls1 += __shfl_xor_sync(0xffffffffu, ls1, 1);
        ls1 += __shfl_xor_sync(0xffffffffu, ls1, 2);
        l0 = l0 * alpha0 + ls0;
        l1 = l1 * alpha1 + ls1;
        m0 = nm0;
        m1 = nm1;
#pragma unroll
        for (int dnt = 0; dnt < 8; dnt++) {
            o[dnt][0] *= alpha0; o[dnt][1] *= alpha0;
            o[dnt][2] *= alpha1; o[dnt][3] *= alpha1;
        }

        // O += P V
#pragma unroll
        for (int kt = 0; kt < 8; kt++) {
#pragma unroll
            for (int dnt = 0; dnt < 8; dnt++) {
                uint32_t b[2];
                int d = dnt * 8 + g;
                b[0] = *reinterpret_cast<const uint32_t*>(&Vt[d][kt * 16 + tg * 2]);
                b[1] = *reinterpret_cast<const uint32_t*>(&Vt[d][kt * 16 + 8 + tg * 2]);
                mma16816(o[dnt], pa[kt], b);
            }
        }
        __syncthreads();
    }

    // write merged-head output a[b,s,h*64+d] as fp16
    float inv0 = 1.f / l0, inv1 = 1.f / l1;
    int b = bh >> 4, h = bh & 15;
    int s0 = qb * AT_BQ + warp * 16 + g;
    size_t r0 = (size_t)(b * SEQ + s0) * DMODEL + h * HDIM;
    size_t r1 = r0 + (size_t)8 * DMODEL;
#pragma unroll
    for (int dnt = 0; dnt < 8; dnt++) {
        int d = dnt * 8 + tg * 2;
        Aout[r0 + d]     = __float2half(o[dnt][0] * inv0);
        Aout[r0 + d + 1] = __float2half(o[dnt][1] * inv0);
        Aout[r1 + d]     = __float2half(o[dnt][2] * inv1);
        Aout[r1 + d + 1] = __float2half(o[dnt][3] * inv1);
    }
}

// --------------------------- residual + layernorm --------------------------
// out = LN(X + Y) * g + b; optionally also emit fp16 copy. One block per row.
__global__ __launch_bounds__(256) void ln_kernel(
    const float* __restrict__ X, const float* __restrict__ Y,
    const float* __restrict__ gg, const float* __restrict__ bb,
    float* __restrict__ out32, __half* __restrict__ out16) {
    const int row = blockIdx.x, tid = threadIdx.x;
    const float* x = X + (size_t)row * DMODEL;
    const float* y = Y + (size_t)row * DMODEL;
    float v[4];
    float s = 0.f;
#pragma unroll
    for (int i = 0; i < 4; i++) {
        int c = tid + i * 256;
        v[i] = x[c] + y[c];
        s += v[i];
    }
    __shared__ float red[8], red2[8];
#pragma unroll
    for (int o = 16; o; o >>= 1) s += __shfl_xor_sync(0xffffffffu, s, o);
    if ((tid & 31) == 0) red[tid >> 5] = s;
    __syncthreads();
    float tot = 0.f;
#pragma unroll
    for (int i = 0; i < 8; i++) tot += red[i];
    float mean = tot * (1.0f / DMODEL);

    float s2 = 0.f;
#pragma unroll
    for (int i = 0; i < 4; i++) {
        float d = v[i] - mean;
        s2 += d * d;
    }
#pragma unroll
    for (int o = 16; o; o >>= 1) s2 += __shfl_xor_sync(0xffffffffu, s2, o);
    if ((tid & 31) == 0) red2[tid >> 5] = s2;
    __syncthreads();
    float tot2 = 0.f;
#pragma unroll
    for (int i = 0; i < 8; i++) tot2 += red2[i];
    float rstd = rsqrtf(tot2 * (1.0f / DMODEL) + 1e-5f);

#pragma unroll
    for (int i = 0; i < 4; i++) {
        int c = tid + i * 256;
        float nv = (v[i] - mean) * rstd * gg[c] + bb[c];
        out32[(size_t)row * DMODEL + c] = nv;
        if (out16) out16[(size_t)row * DMODEL + c] = __float2half(nv);
    }
}

// ------------------------------- host --------------------------------------
extern "C" void kernel_launch(void* const* d_in, const int* in_sizes, int n_in,
                              void* d_out, int out_size) {
    const float* x       = (const float*)d_in[0];
    const float* w_attn  = (const float*)d_in[1];
    const float* b_attn  = (const float*)d_in[2];
    const float* w_aproj = (const float*)d_in[3];
    const float* b_aproj = (const float*)d_in[4];
    const float* g1      = (const float*)d_in[5];
    const float* b1      = (const float*)d_in[6];
    const float* w_fc    = (const float*)d_in[7];
    const float* b_fc    = (const float*)d_in[8];
    const float* w_mproj = (const float*)d_in[9];
    const float* b_mproj = (const float*)d_in[10];
    const float* g2      = (const float*)d_in[11];
    const float* b2      = (const float*)d_in[12];
    float* out = (float*)d_out;

    __half *x16, *wattnT, *waprojT, *wfcT, *wmprojT, *q16, *k16, *v16, *a16, *n16, *h16;
    float *ap32, *n32, *m32;
    cudaGetSymbolAddress((void**)&x16,     g_x16);
    cudaGetSymbolAddress((void**)&wattnT,  g_wattnT);
    cudaGetSymbolAddress((void**)&waprojT, g_waprojT);
    cudaGetSymbolAddress((void**)&wfcT,    g_wfcT);
    cudaGetSymbolAddress((void**)&wmprojT, g_wmprojT);
    cudaGetSymbolAddress((void**)&q16,     g_q16);
    cudaGetSymbolAddress((void**)&k16,     g_k16);
    cudaGetSymbolAddress((void**)&v16,     g_v16);
    cudaGetSymbolAddress((void**)&a16,     g_a16);
    cudaGetSymbolAddress((void**)&n16,     g_n16);
    cudaGetSymbolAddress((void**)&h16,     g_h16);
    cudaGetSymbolAddress((void**)&ap32,    g_ap32);
    cudaGetSymbolAddress((void**)&n32,     g_n32);
    cudaGetSymbolAddress((void**)&m32,     g_m32);

    dim3 tb(32, 8);
    // input + weight conversion (weights transposed to [N][K] fp16)
    cvt_f32_to_f16<<<(ROWS * DMODEL) / 256, 256>>>(x, x16, ROWS * DMODEL);
    transpose_cvt<<<dim3(3 * DMODEL / 32, DMODEL / 32), tb>>>(w_attn,  wattnT,  DMODEL, 3 * DMODEL);
    transpose_cvt<<<dim3(DMODEL / 32,     DMODEL / 32), tb>>>(w_aproj, waprojT, DMODEL, DMODEL);
    transpose_cvt<<<dim3(DFF / 32,        DMODEL / 32), tb>>>(w_fc,    wfcT,    DMODEL, DFF);
    transpose_cvt<<<dim3(DMODEL / 32,     DFF / 32),    tb>>>(w_mproj, wmprojT, DFF,    DMODEL);

    // qkv = x @ w_attn + b_attn  (scattered into per-head q/k/v)
    gemm_kernel<EPI_QKV><<<dim3(3 * DMODEL / GB_BN, ROWS / GB_BM), 256>>>(
        x16, wattnT, b_attn, nullptr, nullptr, q16, k16, v16, ROWS, 3 * DMODEL, DMODEL);

    // causal flash attention
    attn_kernel<<<dim3(SEQ / AT_BQ, BATCH * NHEAD), 256>>>(q16, k16, v16, a16);

    // aproj
    gemm_kernel<EPI_F32><<<dim3(DMODEL / GB_BN, ROWS / GB_BM), 256>>>(
        a16, waprojT, b_aproj, ap32, nullptr, nullptr, nullptr, nullptr,
        ROWS, DMODEL, DMODEL);

    // n = LN(x + aproj)
    ln_kernel<<<ROWS, 256>>>(x, ap32, g1, b1, n32, n16);

    // h = gelu(n @ w_fc + b_fc)
    gemm_kernel<EPI_GELU><<<dim3(DFF / GB_BN, ROWS / GB_BM), 256>>>(
        n16, wfcT, b_fc, nullptr, h16, nullptr, nullptr, nullptr,
        ROWS, DFF, DMODEL);

    // m = h @ w_mproj + b_mproj
    gemm_kernel<EPI_F32><<<dim3(DMODEL / GB_BN, ROWS / GB_BM), 256>>>(
        h16, wmprojT, b_mproj, m32, nullptr, nullptr, nullptr, nullptr,
        ROWS, DMODEL, DFF);

    // out = LN(n + m)
    ln_kernel<<<ROWS, 256>>>(n32, m32, g2, b2, out, nullptr);
}